// round 1
// baseline (speedup 1.0000x reference)
#include <cuda_runtime.h>

// Problem constants
#define TTOK 2048        // B*L tokens
#define BB   2
#define LSEQ 1024
#define DM   1024
#define HH   16
#define HDIM 64
#define EE   8
#define FF   2048
#define AMAX 4608        // 4096 assignments + 8*64 padding
#define MAX_TILES 72

// ---------------- device scratch (static allocation is allowed) -------------
__device__ float g_normed[TTOK * DM];
__device__ float g_alpha[TTOK];
__device__ float g_qkv[TTOK * 3 * DM];
__device__ float g_S[(size_t)32 * LSEQ * LSEQ];   // attention scores, 128 MB
__device__ float g_attnO[TTOK * DM];
__device__ float g_gate[TTOK * DM];
__device__ float g_proj[TTOK * DM];
__device__ float g_xz[TTOK * 2 * DM];
__device__ float g_sact[TTOK * DM];
__device__ float g_ssm[TTOK * DM];
__device__ float g_u[TTOK * DM];
__device__ float g_min[TTOK * DM];                // moe input (ln2)
__device__ int   g_top_idx[TTOK * 2];
__device__ float g_top_w[TTOK * 2];
__device__ int   g_slot[TTOK * 2];
__device__ int   g_count[EE];
__device__ int   g_fill[EE];
__device__ int   g_seg_start[EE];
__device__ int   g_tile_expert[MAX_TILES];
__device__ int   g_tile_row0[MAX_TILES];
__device__ int   g_num_tiles;
__device__ int   g_assign_tok[AMAX];
__device__ float g_H1[(size_t)AMAX * FF];
__device__ float g_H3[(size_t)AMAX * FF];
__device__ float g_Y[(size_t)AMAX * DM];

__device__ __forceinline__ float sigm(float v) { return 1.f / (1.f + expf(-v)); }

// ---------------- elementwise / reduction kernels ---------------------------

__global__ void zero_kernel() {
    int i = blockIdx.x * blockDim.x + threadIdx.x;
    if (i < EE) { g_count[i] = 0; g_fill[i] = 0; }
    if (i < AMAX) g_assign_tok[i] = 0;
}

// layernorm over rows of length 1024; 256 threads/block, one block per row
__global__ void ln_kernel(const float* __restrict__ in, const float* __restrict__ g,
                          const float* __restrict__ b, float* __restrict__ out) {
    int t = blockIdx.x;
    int tid = threadIdx.x;
    const float* row = in + (size_t)t * DM;
    float v[4], s = 0.f, s2 = 0.f;
#pragma unroll
    for (int i = 0; i < 4; i++) {
        v[i] = row[tid + i * 256];
        s += v[i]; s2 += v[i] * v[i];
    }
    __shared__ float sh1[256], sh2[256];
    sh1[tid] = s; sh2[tid] = s2;
    __syncthreads();
    for (int o = 128; o > 0; o >>= 1) {
        if (tid < o) { sh1[tid] += sh1[tid + o]; sh2[tid] += sh2[tid + o]; }
        __syncthreads();
    }
    float mean = sh1[0] * (1.f / DM);
    float var = sh2[0] * (1.f / DM) - mean * mean;
    float inv = rsqrtf(var + 1e-5f);
    float* orow = out + (size_t)t * DM;
#pragma unroll
    for (int i = 0; i < 4; i++) {
        int d = tid + i * 256;
        orow[d] = (v[i] - mean) * inv * g[d] + b[d];
    }
}

// alpha = sigmoid(normed @ Wr[:,0] + br[0])
__global__ void alpha_kernel(const float* __restrict__ Wr, const float* __restrict__ br) {
    int t = blockIdx.x, tid = threadIdx.x;
    float s = 0.f;
#pragma unroll
    for (int i = 0; i < 4; i++) {
        int d = tid + i * 256;
        s += g_normed[(size_t)t * DM + d] * Wr[d * 2];
    }
    __shared__ float sh[256];
    sh[tid] = s; __syncthreads();
    for (int o = 128; o > 0; o >>= 1) {
        if (tid < o) sh[tid] += sh[tid + o];
        __syncthreads();
    }
    if (tid == 0) g_alpha[t] = sigm(sh[0] + br[0]);
}

// row softmax over 1024 elements (attention scores)
__global__ void softmax_kernel() {
    size_t row = blockIdx.x;
    float* p = g_S + row * LSEQ;
    int tid = threadIdx.x;
    float v[4], m = -1e30f;
#pragma unroll
    for (int i = 0; i < 4; i++) { v[i] = p[tid + i * 256]; m = fmaxf(m, v[i]); }
    __shared__ float sh[256];
    sh[tid] = m; __syncthreads();
    for (int o = 128; o > 0; o >>= 1) {
        if (tid < o) sh[tid] = fmaxf(sh[tid], sh[tid + o]);
        __syncthreads();
    }
    m = sh[0]; __syncthreads();
    float s = 0.f;
#pragma unroll
    for (int i = 0; i < 4; i++) { v[i] = expf(v[i] - m); s += v[i]; }
    sh[tid] = s; __syncthreads();
    for (int o = 128; o > 0; o >>= 1) {
        if (tid < o) sh[tid] += sh[tid + o];
        __syncthreads();
    }
    float inv = 1.f / sh[0];
#pragma unroll
    for (int i = 0; i < 4; i++) p[tid + i * 256] = v[i] * inv;
}

// depthwise causal conv (k=4) + silu + gate-by-sigmoid(z)
__global__ void conv_act_kernel(const float* __restrict__ cw, const float* __restrict__ cb) {
    int idx = blockIdx.x * blockDim.x + threadIdx.x;     // over TTOK*DM
    int d = idx & (DM - 1);
    int t = idx >> 10;
    int l = t & (LSEQ - 1);
    int b = t >> 10;
    float y = cb[d];
#pragma unroll
    for (int k = 0; k < 4; k++) {
        int ls = l - 3 + k;
        if (ls >= 0) y += cw[d * 4 + k] * g_xz[((size_t)(b * LSEQ + ls)) * (2 * DM) + d];
    }
    float xc = y * sigm(y);                               // silu
    float z = g_xz[(size_t)t * (2 * DM) + DM + d];
    g_sact[idx] = xc * sigm(z);
}

// blended = ls1*((1-a)*ssm + a*attn);  u = x + blended
__global__ void blend_kernel(const float* __restrict__ x, const float* __restrict__ ls1) {
    int idx = blockIdx.x * blockDim.x + threadIdx.x;
    int t = idx >> 10, d = idx & (DM - 1);
    float a = g_alpha[t];
    float attn = g_proj[idx] * sigm(g_gate[idx]);
    float bl = ls1[d] * ((1.f - a) * g_ssm[idx] + a * attn);
    g_u[idx] = x[idx] + bl;
}

// gating: logits = moe_in @ Wg, softmax(8), top-2, renormalize
__global__ void gating_kernel(const float* __restrict__ Wg) {
    int t = blockIdx.x, tid = threadIdx.x;
    int lane = tid & 31, w = tid >> 5;                    // 8 warps = 8 experts
    float s = 0.f;
    for (int d = lane; d < DM; d += 32)
        s += g_min[(size_t)t * DM + d] * Wg[d * EE + w];
#pragma unroll
    for (int o = 16; o > 0; o >>= 1) s += __shfl_down_sync(0xffffffffu, s, o);
    __shared__ float lg[EE];
    if (lane == 0) lg[w] = s;
    __syncthreads();
    if (tid == 0) {
        float m = lg[0];
        for (int e = 1; e < EE; e++) m = fmaxf(m, lg[e]);
        float p[EE], sum = 0.f;
        for (int e = 0; e < EE; e++) { p[e] = expf(lg[e] - m); sum += p[e]; }
        float inv = 1.f / sum;
        for (int e = 0; e < EE; e++) p[e] *= inv;
        int i0 = 0;
        for (int e = 1; e < EE; e++) if (p[e] > p[i0]) i0 = e;
        int i1 = (i0 == 0) ? 1 : 0;
        for (int e = 0; e < EE; e++) if (e != i0 && p[e] > p[i1]) i1 = e;
        float den = p[i0] + p[i1] + 1e-8f;
        g_top_idx[t * 2] = i0; g_top_idx[t * 2 + 1] = i1;
        g_top_w[t * 2] = p[i0] / den; g_top_w[t * 2 + 1] = p[i1] / den;
        atomicAdd(&g_count[i0], 1);
        atomicAdd(&g_count[i1], 1);
    }
}

// build 64-row-padded expert segments + tile map (single thread; E=8)
__global__ void seg_kernel() {
    if (threadIdx.x == 0 && blockIdx.x == 0) {
        int off = 0, nt = 0;
        for (int e = 0; e < EE; e++) {
            g_seg_start[e] = off;
            int tiles = (g_count[e] + 63) >> 6;
            for (int i = 0; i < tiles; i++) {
                g_tile_expert[nt] = e;
                g_tile_row0[nt] = off + (i << 6);
                nt++;
            }
            off += tiles << 6;
        }
        g_num_tiles = nt;
    }
}

__global__ void scatter_kernel() {
    int t = blockIdx.x * blockDim.x + threadIdx.x;
    if (t >= TTOK) return;
#pragma unroll
    for (int k = 0; k < 2; k++) {
        int e = g_top_idx[t * 2 + k];
        int pos = atomicAdd(&g_fill[e], 1);
        int slot = g_seg_start[e] + pos;
        g_assign_tok[slot] = t;
        g_slot[t * 2 + k] = slot;
    }
}

// h = silu(h1) * h3
__global__ void h_act_kernel() {
    size_t i = (size_t)blockIdx.x * blockDim.x + threadIdx.x;
    float a = g_H1[i], c = g_H3[i];
    g_H1[i] = (a * sigm(a)) * c;
}

// out = x + u + ls2 * (w0*Y[slot0] + w1*Y[slot1])   (= 2x + blended + ls2*moe)
__global__ void combine_kernel(const float* __restrict__ x, const float* __restrict__ ls2,
                               float* __restrict__ out) {
    int idx = blockIdx.x * blockDim.x + threadIdx.x;
    int t = idx >> 10, d = idx & (DM - 1);
    float moe = g_top_w[t * 2] * g_Y[(size_t)g_slot[t * 2] * DM + d]
              + g_top_w[t * 2 + 1] * g_Y[(size_t)g_slot[t * 2 + 1] * DM + d];
    out[idx] = x[idx] + g_u[idx] + ls2[d] * moe;
}

// ---------------- generic tiled SGEMM ---------------------------------------
// C[M,N] = scale * A[M,K] @ B[K,N]; batched via z: off = (z&15)*s1 + (z>>4)*s2
// transB: B(k,n) at Bm[n*ldb + k]
#define BM 64
#define BN 64
#define BKK 16

__global__ __launch_bounds__(256) void gemm_kernel(
    const float* __restrict__ A, int lda, long sA1, long sA2,
    const float* __restrict__ Bm, int ldb, long sB1, long sB2, int transB,
    float* __restrict__ C, int ldc, long sC1, long sC2,
    int K, float scale)
{
    int z = blockIdx.z;
    const float* Ab = A + (long)(z & 15) * sA1 + (long)(z >> 4) * sA2;
    const float* Bb = Bm + (long)(z & 15) * sB1 + (long)(z >> 4) * sB2;
    float* Cb = C + (long)(z & 15) * sC1 + (long)(z >> 4) * sC2;
    int row0 = blockIdx.y * BM, col0 = blockIdx.x * BN;
    __shared__ float As[BKK][BM];
    __shared__ float Bs[BKK][BN];
    int tid = threadIdx.x;
    int tr = tid >> 4, tc = tid & 15;
    float acc[4][4] = {};
    for (int k0 = 0; k0 < K; k0 += BKK) {
        {   // A tile: (m, k0+kq..kq+3), contiguous along k
            int m = tid >> 2, kq = (tid & 3) * 4;
            const float4 p = *reinterpret_cast<const float4*>(Ab + (long)(row0 + m) * lda + k0 + kq);
            As[kq + 0][m] = p.x; As[kq + 1][m] = p.y; As[kq + 2][m] = p.z; As[kq + 3][m] = p.w;
        }
        if (!transB) {
            int k = tid >> 4, nq = (tid & 15) * 4;
            const float4 p = *reinterpret_cast<const float4*>(Bb + (long)(k0 + k) * ldb + col0 + nq);
            *reinterpret_cast<float4*>(&Bs[k][nq]) = p;
        } else {
            int n = tid >> 2, kq = (tid & 3) * 4;
            const float4 p = *reinterpret_cast<const float4*>(Bb + (long)(col0 + n) * ldb + k0 + kq);
            Bs[kq + 0][n] = p.x; Bs[kq + 1][n] = p.y; Bs[kq + 2][n] = p.z; Bs[kq + 3][n] = p.w;
        }
        __syncthreads();
#pragma unroll
        for (int k = 0; k < BKK; k++) {
            float4 a = *reinterpret_cast<const float4*>(&As[k][tr * 4]);
            float4 b = *reinterpret_cast<const float4*>(&Bs[k][tc * 4]);
            float av[4] = {a.x, a.y, a.z, a.w};
            float bv[4] = {b.x, b.y, b.z, b.w};
#pragma unroll
            for (int i = 0; i < 4; i++)
#pragma unroll
                for (int j = 0; j < 4; j++) acc[i][j] += av[i] * bv[j];
        }
        __syncthreads();
    }
#pragma unroll
    for (int i = 0; i < 4; i++) {
        float4 o = make_float4(acc[i][0] * scale, acc[i][1] * scale, acc[i][2] * scale, acc[i][3] * scale);
        *reinterpret_cast<float4*>(Cb + (long)(row0 + tr * 4 + i) * ldc + col0 + tc * 4) = o;
    }
}

// ---------------- grouped gather-GEMM for MoE --------------------------------
// rows come from tile map; A row r -> token g_assign_tok[r] if gather else r
__global__ __launch_bounds__(256) void grouped_gemm_kernel(
    const float* __restrict__ Asrc, int lda, int gather,
    const float* __restrict__ Wbase, long expStride, int ldb,
    float* __restrict__ C, int ldc, int K)
{
    if ((int)blockIdx.y >= g_num_tiles) return;
    int e = g_tile_expert[blockIdx.y];
    int row0 = g_tile_row0[blockIdx.y];
    const float* Bb = Wbase + (long)e * expStride;
    int col0 = blockIdx.x * BN;
    __shared__ float As[BKK][BM];
    __shared__ float Bs[BKK][BN];
    __shared__ int rowmap[BM];
    int tid = threadIdx.x;
    if (tid < BM) rowmap[tid] = gather ? g_assign_tok[row0 + tid] : (row0 + tid);
    __syncthreads();
    int tr = tid >> 4, tc = tid & 15;
    float acc[4][4] = {};
    for (int k0 = 0; k0 < K; k0 += BKK) {
        {
            int m = tid >> 2, kq = (tid & 3) * 4;
            const float4 p = *reinterpret_cast<const float4*>(Asrc + (long)rowmap[m] * lda + k0 + kq);
            As[kq + 0][m] = p.x; As[kq + 1][m] = p.y; As[kq + 2][m] = p.z; As[kq + 3][m] = p.w;
        }
        {
            int k = tid >> 4, nq = (tid & 15) * 4;
            const float4 p = *reinterpret_cast<const float4*>(Bb + (long)(k0 + k) * ldb + col0 + nq);
            *reinterpret_cast<float4*>(&Bs[k][nq]) = p;
        }
        __syncthreads();
#pragma unroll
        for (int k = 0; k < BKK; k++) {
            float4 a = *reinterpret_cast<const float4*>(&As[k][tr * 4]);
            float4 b = *reinterpret_cast<const float4*>(&Bs[k][tc * 4]);
            float av[4] = {a.x, a.y, a.z, a.w};
            float bv[4] = {b.x, b.y, b.z, b.w};
#pragma unroll
            for (int i = 0; i < 4; i++)
#pragma unroll
                for (int j = 0; j < 4; j++) acc[i][j] += av[i] * bv[j];
        }
        __syncthreads();
    }
#pragma unroll
    for (int i = 0; i < 4; i++) {
        float4 o = make_float4(acc[i][0], acc[i][1], acc[i][2], acc[i][3]);
        *reinterpret_cast<float4*>(C + (long)(row0 + tr * 4 + i) * ldc + col0 + tc * 4) = o;
    }
}

// ---------------- host launch -----------------------------------------------

static float* sym(const void* s) {
    void* p = nullptr;
    cudaGetSymbolAddress(&p, s);
    return (float*)p;
}

extern "C" void kernel_launch(void* const* d_in, const int* in_sizes, int n_in,
                              void* d_out, int out_size) {
    const float* x       = (const float*)d_in[0];
    const float* Wr      = (const float*)d_in[1];
    const float* br      = (const float*)d_in[2];
    // d_in[3] = step_bias: provably irrelevant (halting weights telescope to 1)
    const float* ln1_g   = (const float*)d_in[4];
    const float* ln1_b   = (const float*)d_in[5];
    const float* ln2_g   = (const float*)d_in[6];
    const float* ln2_b   = (const float*)d_in[7];
    const float* ls1     = (const float*)d_in[8];
    const float* ls2     = (const float*)d_in[9];
    const float* Wqkv    = (const float*)d_in[10];
    const float* Wout    = (const float*)d_in[11];
    const float* Wgate   = (const float*)d_in[12];
    const float* Win_ssm = (const float*)d_in[13];
    const float* conv_w  = (const float*)d_in[14];
    const float* conv_b  = (const float*)d_in[15];
    const float* Wout_ssm= (const float*)d_in[16];
    const float* Wg      = (const float*)d_in[17];
    const float* W1      = (const float*)d_in[18];
    const float* W2      = (const float*)d_in[19];
    const float* W3      = (const float*)d_in[20];
    float* out = (float*)d_out;

    float* p_normed = sym(g_normed);
    float* p_qkv    = sym(g_qkv);
    float* p_S      = sym(g_S);
    float* p_attnO  = sym(g_attnO);
    float* p_gate   = sym(g_gate);
    float* p_proj   = sym(g_proj);
    float* p_xz     = sym(g_xz);
    float* p_sact   = sym(g_sact);
    float* p_ssm    = sym(g_ssm);
    float* p_u      = sym(g_u);
    float* p_min    = sym(g_min);
    float* p_H1     = sym(g_H1);
    float* p_H3     = sym(g_H3);
    float* p_Y      = sym(g_Y);

    const int TD = TTOK * DM;

    zero_kernel<<<(AMAX + 255) / 256, 256>>>();
    ln_kernel<<<TTOK, 256>>>(x, ln1_g, ln1_b, p_normed);
    alpha_kernel<<<TTOK, 256>>>(Wr, br);

    // qkv = normed @ Wqkv  [2048 x 3072 x 1024]
    gemm_kernel<<<dim3(48, 32, 1), 256>>>(p_normed, DM, 0, 0, Wqkv, 3 * DM, 0, 0, 0,
                                          p_qkv, 3 * DM, 0, 0, DM, 1.f);
    // S = Q @ K^T * 0.125 per (b,h): 32 batches, M=N=1024, K=64
    gemm_kernel<<<dim3(16, 16, 32), 256>>>(
        p_qkv, 3 * DM, HDIM, (long)LSEQ * 3 * DM,
        p_qkv + DM, 3 * DM, HDIM, (long)LSEQ * 3 * DM, 1,
        p_S, LSEQ, (long)LSEQ * LSEQ, (long)16 * LSEQ * LSEQ,
        HDIM, 0.125f);
    softmax_kernel<<<32 * LSEQ, 256>>>();
    // O = P @ V: M=1024, N=64, K=1024, write into [T,D] layout
    gemm_kernel<<<dim3(1, 16, 32), 256>>>(
        p_S, LSEQ, (long)LSEQ * LSEQ, (long)16 * LSEQ * LSEQ,
        p_qkv + 2 * DM, 3 * DM, HDIM, (long)LSEQ * 3 * DM, 0,
        p_attnO, DM, HDIM, (long)LSEQ * DM,
        LSEQ, 1.f);
    // gate = normed @ Wgate; proj = attnO @ Wout
    gemm_kernel<<<dim3(16, 32, 1), 256>>>(p_normed, DM, 0, 0, Wgate, DM, 0, 0, 0,
                                          p_gate, DM, 0, 0, DM, 1.f);
    gemm_kernel<<<dim3(16, 32, 1), 256>>>(p_attnO, DM, 0, 0, Wout, DM, 0, 0, 0,
                                          p_proj, DM, 0, 0, DM, 1.f);
    // xz = normed @ Win_ssm [2048 x 2048 x 1024]
    gemm_kernel<<<dim3(32, 32, 1), 256>>>(p_normed, DM, 0, 0, Win_ssm, 2 * DM, 0, 0, 0,
                                          p_xz, 2 * DM, 0, 0, DM, 1.f);
    conv_act_kernel<<<TD / 256, 256>>>(conv_w, conv_b);
    gemm_kernel<<<dim3(16, 32, 1), 256>>>(p_sact, DM, 0, 0, Wout_ssm, DM, 0, 0, 0,
                                          p_ssm, DM, 0, 0, DM, 1.f);
    blend_kernel<<<TD / 256, 256>>>(x, ls1);
    ln_kernel<<<TTOK, 256>>>(p_u, ln2_g, ln2_b, p_min);

    // MoE: gate -> route -> grouped gemms -> combine
    gating_kernel<<<TTOK, 256>>>(Wg);
    seg_kernel<<<1, 32>>>();
    scatter_kernel<<<TTOK / 256, 256>>>();
    grouped_gemm_kernel<<<dim3(FF / 64, MAX_TILES), 256>>>(p_min, DM, 1, W1, (long)DM * FF, FF,
                                                           p_H1, FF, DM);
    grouped_gemm_kernel<<<dim3(FF / 64, MAX_TILES), 256>>>(p_min, DM, 1, W3, (long)DM * FF, FF,
                                                           p_H3, FF, DM);
    h_act_kernel<<<(int)(((size_t)AMAX * FF) / 256), 256>>>();
    grouped_gemm_kernel<<<dim3(DM / 64, MAX_TILES), 256>>>(p_H1, FF, 0, W2, (long)FF * DM, DM,
                                                           p_Y, DM, FF);
    combine_kernel<<<TD / 256, 256>>>(x, ls2, out);
}

// round 2
// speedup vs baseline: 4.2479x; 4.2479x over previous
#include <cuda_runtime.h>
#include <cuda_bf16.h>
#include <cstdint>

// Problem constants
#define TTOK 2048        // B*L tokens
#define LSEQ 1024
#define DM   1024
#define HH   16
#define HDIM 64
#define EE   8
#define FF   2048
#define AMAX 5120        // 4096 assignments + 8*128 padding
#define MAX_TILES 48

typedef __nv_bfloat16 bf16;

// ---------------- device scratch ---------------------------------------------
__device__ bf16  g_normedb[TTOK * DM];
__device__ float g_alpha[TTOK];
__device__ bf16  g_qkvb[TTOK * 3 * DM];
__device__ float g_S[(size_t)32 * LSEQ * LSEQ];   // attention scores fp32
__device__ bf16  g_Pb[(size_t)32 * LSEQ * LSEQ];  // probs bf16
__device__ bf16  g_attnOb[TTOK * DM];
__device__ float g_gate[TTOK * DM];
__device__ float g_proj[TTOK * DM];
__device__ float g_xz[TTOK * 2 * DM];
__device__ bf16  g_sactb[TTOK * DM];
__device__ float g_ssm[TTOK * DM];
__device__ float g_u[TTOK * DM];
__device__ bf16  g_minb[TTOK * DM];
__device__ int   g_top_idx[TTOK * 2];
__device__ float g_top_w[TTOK * 2];
__device__ int   g_slot[TTOK * 2];
__device__ int   g_count[EE];
__device__ int   g_fill[EE];
__device__ int   g_seg_start[EE];
__device__ int   g_tile_expert[MAX_TILES];
__device__ int   g_tile_row0[MAX_TILES];
__device__ int   g_num_tiles;
__device__ int   g_assign_tok[AMAX];
__device__ float g_H1[(size_t)AMAX * FF];
__device__ float g_H3[(size_t)AMAX * FF];
__device__ bf16  g_Hb[(size_t)AMAX * FF];
__device__ float g_Y[(size_t)AMAX * DM];

// bf16 weight copies (converted once per launch)
__device__ bf16 g_Wqkvb[DM * 3 * DM];
__device__ bf16 g_Woutb[DM * DM];
__device__ bf16 g_Wgateb[DM * DM];
__device__ bf16 g_Winb[DM * 2 * DM];
__device__ bf16 g_Woutsb[DM * DM];
__device__ bf16 g_W1b[(size_t)EE * DM * FF];
__device__ bf16 g_W2b[(size_t)EE * FF * DM];
__device__ bf16 g_W3b[(size_t)EE * DM * FF];

__device__ __forceinline__ float sigm(float v) { return 1.f / (1.f + expf(-v)); }

// ---------------- mma helpers ------------------------------------------------

__device__ __forceinline__ unsigned smaddr(const void* p) {
    return (unsigned)__cvta_generic_to_shared(p);
}

#define LDSM4(R0,R1,R2,R3,ADDR) \
    asm volatile("ldmatrix.sync.aligned.m8n8.x4.shared.b16 {%0,%1,%2,%3}, [%4];" \
        : "=r"(R0),"=r"(R1),"=r"(R2),"=r"(R3) : "r"(ADDR))

#define LDSM4T(R0,R1,R2,R3,ADDR) \
    asm volatile("ldmatrix.sync.aligned.m8n8.x4.trans.shared.b16 {%0,%1,%2,%3}, [%4];" \
        : "=r"(R0),"=r"(R1),"=r"(R2),"=r"(R3) : "r"(ADDR))

__device__ __forceinline__ void mma16816(float* d, const unsigned* a, const unsigned* b) {
    asm volatile(
        "mma.sync.aligned.m16n8k16.row.col.f32.bf16.bf16.f32 "
        "{%0,%1,%2,%3},{%4,%5,%6,%7},{%8,%9},{%0,%1,%2,%3};"
        : "+f"(d[0]), "+f"(d[1]), "+f"(d[2]), "+f"(d[3])
        : "r"(a[0]), "r"(a[1]), "r"(a[2]), "r"(a[3]), "r"(b[0]), "r"(b[1]));
}

__device__ __forceinline__ void store2(float* p, float x, float y) {
    *reinterpret_cast<float2*>(p) = make_float2(x, y);
}
__device__ __forceinline__ void store2(bf16* p, float x, float y) {
    *reinterpret_cast<__nv_bfloat162*>(p) = __floats2bfloat162_rn(x, y);
}

// ---------------- bf16 tensor-core GEMM --------------------------------------
// C[M,N] = scale * A @ op(B); batched via z: off = (z&15)*s1 + (z>>4)*s2
// TRANSB: B(k,n) = Bm[n*ldb + k]
template<int BN, bool TRANSB, typename OutT>
__global__ __launch_bounds__(256) void mma_gemm(
    const bf16* __restrict__ A, int lda, long sA1, long sA2,
    const bf16* __restrict__ B, int ldb, long sB1, long sB2,
    OutT* __restrict__ C, int ldc, long sC1, long sC2, int K, float scale)
{
    constexpr int BM = 128, BK = 64;
    constexpr int WN = BN / 2;        // 2 warp cols
    constexpr int NT = WN / 8;        // n8-tiles per warp
    int z = blockIdx.z;
    const bf16* Ab = A + (long)(z & 15) * sA1 + (long)(z >> 4) * sA2;
    const bf16* Bb = B + (long)(z & 15) * sB1 + (long)(z >> 4) * sB2;
    OutT* Cb = C + (long)(z & 15) * sC1 + (long)(z >> 4) * sC2;
    int row0 = blockIdx.y * BM, col0 = blockIdx.x * BN;

    __shared__ alignas(16) bf16 As[BM][BK + 8];
    constexpr int BROWS = TRANSB ? BN : BK;
    constexpr int BST   = TRANSB ? (BK + 8) : (BN + 8);
    __shared__ alignas(16) bf16 Bs[BROWS][BST];

    int tid = threadIdx.x, lane = tid & 31, wid = tid >> 5;
    int wm = wid & 3, wn = wid >> 2;

    float acc[2][NT][4];
#pragma unroll
    for (int i = 0; i < 2; i++)
#pragma unroll
        for (int j = 0; j < NT; j++)
#pragma unroll
            for (int r = 0; r < 4; r++) acc[i][j][r] = 0.f;

    for (int k0 = 0; k0 < K; k0 += BK) {
#pragma unroll
        for (int v = tid; v < BM * BK / 8; v += 256) {
            int r = v >> 3, c = (v & 7) * 8;
            *reinterpret_cast<uint4*>(&As[r][c]) =
                *reinterpret_cast<const uint4*>(Ab + (long)(row0 + r) * lda + k0 + c);
        }
        if constexpr (TRANSB) {
#pragma unroll
            for (int v = tid; v < BN * BK / 8; v += 256) {
                int r = v >> 3, c = (v & 7) * 8;
                *reinterpret_cast<uint4*>(&Bs[r][c]) =
                    *reinterpret_cast<const uint4*>(Bb + (long)(col0 + r) * ldb + k0 + c);
            }
        } else {
#pragma unroll
            for (int v = tid; v < BK * BN / 8; v += 256) {
                int r = v / (BN / 8), c = (v % (BN / 8)) * 8;
                *reinterpret_cast<uint4*>(&Bs[r][c]) =
                    *reinterpret_cast<const uint4*>(Bb + (long)(k0 + r) * ldb + col0 + c);
            }
        }
        __syncthreads();

#pragma unroll
        for (int ks = 0; ks < BK / 16; ks++) {
            unsigned afr[2][4];
#pragma unroll
            for (int mi = 0; mi < 2; mi++) {
                const bf16* p = &As[wm * 32 + mi * 16 + (lane & 15)][ks * 16 + (lane >> 4) * 8];
                LDSM4(afr[mi][0], afr[mi][1], afr[mi][2], afr[mi][3], smaddr(p));
            }
            unsigned bfr[NT][2];
#pragma unroll
            for (int njp = 0; njp < NT / 2; njp++) {
                int nb = wn * WN + njp * 16;
                if constexpr (TRANSB) {
                    const bf16* p = &Bs[nb + (lane & 7) + ((lane >> 4) << 3)]
                                       [ks * 16 + ((lane >> 3) & 1) * 8];
                    LDSM4(bfr[2*njp][0], bfr[2*njp][1], bfr[2*njp+1][0], bfr[2*njp+1][1], smaddr(p));
                } else {
                    const bf16* p = &Bs[ks * 16 + (lane & 7) + ((lane >> 3) & 1) * 8]
                                       [nb + (lane >> 4) * 8];
                    LDSM4T(bfr[2*njp][0], bfr[2*njp][1], bfr[2*njp+1][0], bfr[2*njp+1][1], smaddr(p));
                }
            }
#pragma unroll
            for (int mi = 0; mi < 2; mi++)
#pragma unroll
                for (int nj = 0; nj < NT; nj++)
                    mma16816(acc[mi][nj], afr[mi], bfr[nj]);
        }
        __syncthreads();
    }

    int gid = lane >> 2, tig = lane & 3;
#pragma unroll
    for (int mi = 0; mi < 2; mi++)
#pragma unroll
        for (int nj = 0; nj < NT; nj++) {
            int r = row0 + wm * 32 + mi * 16 + gid;
            int c = col0 + wn * WN + nj * 8 + tig * 2;
            store2(Cb + (long)r * ldc + c, acc[mi][nj][0] * scale, acc[mi][nj][1] * scale);
            store2(Cb + (long)(r + 8) * ldc + c, acc[mi][nj][2] * scale, acc[mi][nj][3] * scale);
        }
}

// ---------------- grouped (MoE) bf16 GEMM ------------------------------------
template<bool GATHER>
__global__ __launch_bounds__(256) void grouped_mma_gemm(
    const bf16* __restrict__ Asrc, int lda,
    const bf16* __restrict__ Wbase, long expStride, int ldb,
    float* __restrict__ C, int ldc, int K)
{
    constexpr int BM = 128, BN = 128, BK = 64;
    constexpr int WN = 64, NT = 8;
    if ((int)blockIdx.y >= g_num_tiles) return;
    int e = g_tile_expert[blockIdx.y];
    int row0 = g_tile_row0[blockIdx.y];
    const bf16* Bb = Wbase + (long)e * expStride;
    int col0 = blockIdx.x * BN;

    __shared__ alignas(16) bf16 As[BM][BK + 8];
    __shared__ alignas(16) bf16 Bs[BK][BN + 8];
    __shared__ int rowmap[BM];

    int tid = threadIdx.x, lane = tid & 31, wid = tid >> 5;
    int wm = wid & 3, wn = wid >> 2;
    if (tid < BM) rowmap[tid] = GATHER ? g_assign_tok[row0 + tid] : (row0 + tid);
    __syncthreads();

    float acc[2][NT][4];
#pragma unroll
    for (int i = 0; i < 2; i++)
#pragma unroll
        for (int j = 0; j < NT; j++)
#pragma unroll
            for (int r = 0; r < 4; r++) acc[i][j][r] = 0.f;

    for (int k0 = 0; k0 < K; k0 += BK) {
#pragma unroll
        for (int v = tid; v < BM * BK / 8; v += 256) {
            int r = v >> 3, c = (v & 7) * 8;
            *reinterpret_cast<uint4*>(&As[r][c]) =
                *reinterpret_cast<const uint4*>(Asrc + (long)rowmap[r] * lda + k0 + c);
        }
#pragma unroll
        for (int v = tid; v < BK * BN / 8; v += 256) {
            int r = v >> 4, c = (v & 15) * 8;
            *reinterpret_cast<uint4*>(&Bs[r][c]) =
                *reinterpret_cast<const uint4*>(Bb + (long)(k0 + r) * ldb + col0 + c);
        }
        __syncthreads();

#pragma unroll
        for (int ks = 0; ks < BK / 16; ks++) {
            unsigned afr[2][4];
#pragma unroll
            for (int mi = 0; mi < 2; mi++) {
                const bf16* p = &As[wm * 32 + mi * 16 + (lane & 15)][ks * 16 + (lane >> 4) * 8];
                LDSM4(afr[mi][0], afr[mi][1], afr[mi][2], afr[mi][3], smaddr(p));
            }
            unsigned bfr[NT][2];
#pragma unroll
            for (int njp = 0; njp < NT / 2; njp++) {
                int nb = wn * WN + njp * 16;
                const bf16* p = &Bs[ks * 16 + (lane & 7) + ((lane >> 3) & 1) * 8]
                                   [nb + (lane >> 4) * 8];
                LDSM4T(bfr[2*njp][0], bfr[2*njp][1], bfr[2*njp+1][0], bfr[2*njp+1][1], smaddr(p));
            }
#pragma unroll
            for (int mi = 0; mi < 2; mi++)
#pragma unroll
                for (int nj = 0; nj < NT; nj++)
                    mma16816(acc[mi][nj], afr[mi], bfr[nj]);
        }
        __syncthreads();
    }

    int gid = lane >> 2, tig = lane & 3;
#pragma unroll
    for (int mi = 0; mi < 2; mi++)
#pragma unroll
        for (int nj = 0; nj < NT; nj++) {
            int r = row0 + wm * 32 + mi * 16 + gid;
            int c = col0 + wn * WN + nj * 8 + tig * 2;
            store2(C + (long)r * ldc + c, acc[mi][nj][0], acc[mi][nj][1]);
            store2(C + (long)(r + 8) * ldc + c, acc[mi][nj][2], acc[mi][nj][3]);
        }
}

// ---------------- elementwise / reduction kernels ----------------------------

__global__ void zero_kernel() {
    int i = blockIdx.x * blockDim.x + threadIdx.x;
    if (i < EE) { g_count[i] = 0; g_fill[i] = 0; }
    if (i < AMAX) g_assign_tok[i] = 0;
}

__global__ void cvt_kernel(const float4* __restrict__ src, bf16* __restrict__ dst, int n4) {
    int i = blockIdx.x * blockDim.x + threadIdx.x;
    if (i < n4) {
        float4 v = src[i];
        reinterpret_cast<__nv_bfloat162*>(dst)[i * 2]     = __floats2bfloat162_rn(v.x, v.y);
        reinterpret_cast<__nv_bfloat162*>(dst)[i * 2 + 1] = __floats2bfloat162_rn(v.z, v.w);
    }
}

// layernorm over rows of 1024; bf16 output
__global__ void ln_kernel(const float* __restrict__ in, const float* __restrict__ g,
                          const float* __restrict__ b, bf16* __restrict__ out) {
    int t = blockIdx.x, tid = threadIdx.x;
    const float* row = in + (size_t)t * DM;
    float v[4], s = 0.f, s2 = 0.f;
#pragma unroll
    for (int i = 0; i < 4; i++) {
        v[i] = row[tid + i * 256];
        s += v[i]; s2 += v[i] * v[i];
    }
    __shared__ float sh1[256], sh2[256];
    sh1[tid] = s; sh2[tid] = s2;
    __syncthreads();
    for (int o = 128; o > 0; o >>= 1) {
        if (tid < o) { sh1[tid] += sh1[tid + o]; sh2[tid] += sh2[tid + o]; }
        __syncthreads();
    }
    float mean = sh1[0] * (1.f / DM);
    float var = sh2[0] * (1.f / DM) - mean * mean;
    float inv = rsqrtf(var + 1e-5f);
    bf16* orow = out + (size_t)t * DM;
#pragma unroll
    for (int i = 0; i < 4; i++) {
        int d = tid + i * 256;
        orow[d] = __float2bfloat16((v[i] - mean) * inv * g[d] + b[d]);
    }
}

__global__ void alpha_kernel(const float* __restrict__ Wr, const float* __restrict__ br) {
    int t = blockIdx.x, tid = threadIdx.x;
    float s = 0.f;
#pragma unroll
    for (int i = 0; i < 4; i++) {
        int d = tid + i * 256;
        s += __bfloat162float(g_normedb[(size_t)t * DM + d]) * Wr[d * 2];
    }
    __shared__ float sh[256];
    sh[tid] = s; __syncthreads();
    for (int o = 128; o > 0; o >>= 1) {
        if (tid < o) sh[tid] += sh[tid + o];
        __syncthreads();
    }
    if (tid == 0) g_alpha[t] = sigm(sh[0] + br[0]);
}

__global__ void softmax_kernel() {
    size_t row = blockIdx.x;
    const float* p = g_S + row * LSEQ;
    bf16* q = g_Pb + row * LSEQ;
    int tid = threadIdx.x;
    float v[4], m = -1e30f;
#pragma unroll
    for (int i = 0; i < 4; i++) { v[i] = p[tid + i * 256]; m = fmaxf(m, v[i]); }
    __shared__ float sh[256];
    sh[tid] = m; __syncthreads();
    for (int o = 128; o > 0; o >>= 1) {
        if (tid < o) sh[tid] = fmaxf(sh[tid], sh[tid + o]);
        __syncthreads();
    }
    m = sh[0]; __syncthreads();
    float s = 0.f;
#pragma unroll
    for (int i = 0; i < 4; i++) { v[i] = expf(v[i] - m); s += v[i]; }
    sh[tid] = s; __syncthreads();
    for (int o = 128; o > 0; o >>= 1) {
        if (tid < o) sh[tid] += sh[tid + o];
        __syncthreads();
    }
    float inv = 1.f / sh[0];
#pragma unroll
    for (int i = 0; i < 4; i++) q[tid + i * 256] = __float2bfloat16(v[i] * inv);
}

__global__ void conv_act_kernel(const float* __restrict__ cw, const float* __restrict__ cb) {
    int idx = blockIdx.x * blockDim.x + threadIdx.x;
    int d = idx & (DM - 1);
    int t = idx >> 10;
    int l = t & (LSEQ - 1);
    int b = t >> 10;
    float y = cb[d];
#pragma unroll
    for (int k = 0; k < 4; k++) {
        int ls = l - 3 + k;
        if (ls >= 0) y += cw[d * 4 + k] * g_xz[((size_t)(b * LSEQ + ls)) * (2 * DM) + d];
    }
    float xc = y * sigm(y);
    float z = g_xz[(size_t)t * (2 * DM) + DM + d];
    g_sactb[idx] = __float2bfloat16(xc * sigm(z));
}

__global__ void blend_kernel(const float* __restrict__ x, const float* __restrict__ ls1) {
    int idx = blockIdx.x * blockDim.x + threadIdx.x;
    int t = idx >> 10, d = idx & (DM - 1);
    float a = g_alpha[t];
    float attn = g_proj[idx] * sigm(g_gate[idx]);
    float bl = ls1[d] * ((1.f - a) * g_ssm[idx] + a * attn);
    g_u[idx] = x[idx] + bl;
}

__global__ void gating_kernel(const float* __restrict__ Wg) {
    int t = blockIdx.x, tid = threadIdx.x;
    int lane = tid & 31, w = tid >> 5;
    float s = 0.f;
    for (int d = lane; d < DM; d += 32)
        s += __bfloat162float(g_minb[(size_t)t * DM + d]) * Wg[d * EE + w];
#pragma unroll
    for (int o = 16; o > 0; o >>= 1) s += __shfl_down_sync(0xffffffffu, s, o);
    __shared__ float lg[EE];
    if (lane == 0) lg[w] = s;
    __syncthreads();
    if (tid == 0) {
        float m = lg[0];
        for (int e = 1; e < EE; e++) m = fmaxf(m, lg[e]);
        float p[EE], sum = 0.f;
        for (int e = 0; e < EE; e++) { p[e] = expf(lg[e] - m); sum += p[e]; }
        float inv = 1.f / sum;
        for (int e = 0; e < EE; e++) p[e] *= inv;
        int i0 = 0;
        for (int e = 1; e < EE; e++) if (p[e] > p[i0]) i0 = e;
        int i1 = (i0 == 0) ? 1 : 0;
        for (int e = 0; e < EE; e++) if (e != i0 && p[e] > p[i1]) i1 = e;
        float den = p[i0] + p[i1] + 1e-8f;
        g_top_idx[t * 2] = i0; g_top_idx[t * 2 + 1] = i1;
        g_top_w[t * 2] = p[i0] / den; g_top_w[t * 2 + 1] = p[i1] / den;
        atomicAdd(&g_count[i0], 1);
        atomicAdd(&g_count[i1], 1);
    }
}

__global__ void seg_kernel() {
    if (threadIdx.x == 0 && blockIdx.x == 0) {
        int off = 0, nt = 0;
        for (int e = 0; e < EE; e++) {
            g_seg_start[e] = off;
            int tiles = (g_count[e] + 127) >> 7;
            for (int i = 0; i < tiles; i++) {
                g_tile_expert[nt] = e;
                g_tile_row0[nt] = off + (i << 7);
                nt++;
            }
            off += tiles << 7;
        }
        g_num_tiles = nt;
    }
}

__global__ void scatter_kernel() {
    int t = blockIdx.x * blockDim.x + threadIdx.x;
    if (t >= TTOK) return;
#pragma unroll
    for (int k = 0; k < 2; k++) {
        int e = g_top_idx[t * 2 + k];
        int pos = atomicAdd(&g_fill[e], 1);
        int slot = g_seg_start[e] + pos;
        g_assign_tok[slot] = t;
        g_slot[t * 2 + k] = slot;
    }
}

__global__ void h_act_kernel() {
    size_t i = (size_t)blockIdx.x * blockDim.x + threadIdx.x;
    float a = g_H1[i], c = g_H3[i];
    g_Hb[i] = __float2bfloat16((a * sigm(a)) * c);
}

__global__ void combine_kernel(const float* __restrict__ x, const float* __restrict__ ls2,
                               float* __restrict__ out) {
    int idx = blockIdx.x * blockDim.x + threadIdx.x;
    int t = idx >> 10, d = idx & (DM - 1);
    float moe = g_top_w[t * 2] * g_Y[(size_t)g_slot[t * 2] * DM + d]
              + g_top_w[t * 2 + 1] * g_Y[(size_t)g_slot[t * 2 + 1] * DM + d];
    out[idx] = x[idx] + g_u[idx] + ls2[d] * moe;
}

// ---------------- host launch -------------------------------------------------

template <typename T>
static T* sym(const void* s) {
    void* p = nullptr;
    cudaGetSymbolAddress(&p, s);
    return (T*)p;
}

static void cvt(const float* src, bf16* dst, size_t n) {
    int n4 = (int)(n / 4);
    cvt_kernel<<<(n4 + 255) / 256, 256>>>((const float4*)src, dst, n4);
}

extern "C" void kernel_launch(void* const* d_in, const int* in_sizes, int n_in,
                              void* d_out, int out_size) {
    const float* x       = (const float*)d_in[0];
    const float* Wr      = (const float*)d_in[1];
    const float* br      = (const float*)d_in[2];
    const float* ln1_g   = (const float*)d_in[4];
    const float* ln1_b   = (const float*)d_in[5];
    const float* ln2_g   = (const float*)d_in[6];
    const float* ln2_b   = (const float*)d_in[7];
    const float* ls1     = (const float*)d_in[8];
    const float* ls2     = (const float*)d_in[9];
    const float* Wqkv    = (const float*)d_in[10];
    const float* Wout    = (const float*)d_in[11];
    const float* Wgate   = (const float*)d_in[12];
    const float* Win_ssm = (const float*)d_in[13];
    const float* conv_w  = (const float*)d_in[14];
    const float* conv_b  = (const float*)d_in[15];
    const float* Wout_ssm= (const float*)d_in[16];
    const float* Wg      = (const float*)d_in[17];
    const float* W1      = (const float*)d_in[18];
    const float* W2      = (const float*)d_in[19];
    const float* W3      = (const float*)d_in[20];
    float* out = (float*)d_out;

    bf16*  p_normedb = sym<bf16>(g_normedb);
    bf16*  p_qkvb    = sym<bf16>(g_qkvb);
    float* p_S       = sym<float>(g_S);
    bf16*  p_Pb      = sym<bf16>(g_Pb);
    bf16*  p_attnOb  = sym<bf16>(g_attnOb);
    float* p_gate    = sym<float>(g_gate);
    float* p_proj    = sym<float>(g_proj);
    float* p_xz      = sym<float>(g_xz);
    bf16*  p_sactb   = sym<bf16>(g_sactb);
    float* p_ssm     = sym<float>(g_ssm);
    float* p_u       = sym<float>(g_u);
    bf16*  p_minb    = sym<bf16>(g_minb);
    float* p_H1      = sym<float>(g_H1);
    float* p_H3      = sym<float>(g_H3);
    bf16*  p_Hb      = sym<bf16>(g_Hb);
    float* p_Y       = sym<float>(g_Y);
    bf16*  p_Wqkvb   = sym<bf16>(g_Wqkvb);
    bf16*  p_Woutb   = sym<bf16>(g_Woutb);
    bf16*  p_Wgateb  = sym<bf16>(g_Wgateb);
    bf16*  p_Winb    = sym<bf16>(g_Winb);
    bf16*  p_Woutsb  = sym<bf16>(g_Woutsb);
    bf16*  p_W1b     = sym<bf16>(g_W1b);
    bf16*  p_W2b     = sym<bf16>(g_W2b);
    bf16*  p_W3b     = sym<bf16>(g_W3b);

    const int TD = TTOK * DM;
    const long LL = (long)LSEQ * LSEQ;

    zero_kernel<<<(AMAX + 255) / 256, 256>>>();
    cvt(Wqkv, p_Wqkvb, (size_t)DM * 3 * DM);
    cvt(Wout, p_Woutb, (size_t)DM * DM);
    cvt(Wgate, p_Wgateb, (size_t)DM * DM);
    cvt(Win_ssm, p_Winb, (size_t)DM * 2 * DM);
    cvt(Wout_ssm, p_Woutsb, (size_t)DM * DM);
    cvt(W1, p_W1b, (size_t)EE * DM * FF);
    cvt(W2, p_W2b, (size_t)EE * FF * DM);
    cvt(W3, p_W3b, (size_t)EE * DM * FF);

    ln_kernel<<<TTOK, 256>>>(x, ln1_g, ln1_b, p_normedb);
    alpha_kernel<<<TTOK, 256>>>(Wr, br);

    // qkv = normed @ Wqkv -> bf16
    mma_gemm<128, false, bf16><<<dim3(24, 16, 1), 256>>>(
        p_normedb, DM, 0, 0, p_Wqkvb, 3 * DM, 0, 0,
        p_qkvb, 3 * DM, 0, 0, DM, 1.f);
    // S = Q @ K^T * 0.125 (32 batches)
    mma_gemm<128, true, float><<<dim3(8, 8, 32), 256>>>(
        p_qkvb, 3 * DM, HDIM, (long)LSEQ * 3 * DM,
        p_qkvb + DM, 3 * DM, HDIM, (long)LSEQ * 3 * DM,
        p_S, LSEQ, LL, 16 * LL, HDIM, 0.125f);
    softmax_kernel<<<32 * LSEQ, 256>>>();
    // O = P @ V -> bf16 [T,D]
    mma_gemm<64, false, bf16><<<dim3(1, 8, 32), 256>>>(
        p_Pb, LSEQ, LL, 16 * LL,
        p_qkvb + 2 * DM, 3 * DM, HDIM, (long)LSEQ * 3 * DM,
        p_attnOb, DM, HDIM, (long)LSEQ * DM, LSEQ, 1.f);
    // gate / proj
    mma_gemm<128, false, float><<<dim3(8, 16, 1), 256>>>(
        p_normedb, DM, 0, 0, p_Wgateb, DM, 0, 0, p_gate, DM, 0, 0, DM, 1.f);
    mma_gemm<128, false, float><<<dim3(8, 16, 1), 256>>>(
        p_attnOb, DM, 0, 0, p_Woutb, DM, 0, 0, p_proj, DM, 0, 0, DM, 1.f);
    // xz = normed @ Win_ssm
    mma_gemm<128, false, float><<<dim3(16, 16, 1), 256>>>(
        p_normedb, DM, 0, 0, p_Winb, 2 * DM, 0, 0, p_xz, 2 * DM, 0, 0, DM, 1.f);
    conv_act_kernel<<<TD / 256, 256>>>(conv_w, conv_b);
    mma_gemm<128, false, float><<<dim3(8, 16, 1), 256>>>(
        p_sactb, DM, 0, 0, p_Woutsb, DM, 0, 0, p_ssm, DM, 0, 0, DM, 1.f);
    blend_kernel<<<TD / 256, 256>>>(x, ls1);
    ln_kernel<<<TTOK, 256>>>(p_u, ln2_g, ln2_b, p_minb);

    // MoE
    gating_kernel<<<TTOK, 256>>>(Wg);
    seg_kernel<<<1, 32>>>();
    scatter_kernel<<<TTOK / 256, 256>>>();
    grouped_mma_gemm<true><<<dim3(FF / 128, MAX_TILES), 256>>>(
        p_minb, DM, p_W1b, (long)DM * FF, FF, p_H1, FF, DM);
    grouped_mma_gemm<true><<<dim3(FF / 128, MAX_TILES), 256>>>(
        p_minb, DM, p_W3b, (long)DM * FF, FF, p_H3, FF, DM);
    h_act_kernel<<<(int)(((size_t)AMAX * FF) / 256), 256>>>();
    grouped_mma_gemm<false><<<dim3(DM / 128, MAX_TILES), 256>>>(
        p_Hb, FF, p_W2b, (long)FF * DM, DM, p_Y, DM, FF);
    combine_kernel<<<TD / 256, 256>>>(x, ls2, out);
}

// round 3
// speedup vs baseline: 5.7803x; 1.3607x over previous
#include <cuda_runtime.h>
#include <cuda_bf16.h>
#include <cstdint>

#define TTOK 2048
#define LSEQ 1024
#define DM   1024
#define HH   16
#define HDIM 64
#define EE   8
#define FF   2048
#define AMAX 5120
#define MAX_TILES 40

typedef __nv_bfloat16 bf16;

// ---------------- device scratch ---------------------------------------------
__device__ bf16  g_normedb[TTOK * DM];
__device__ float g_alpha[TTOK];
__device__ bf16  g_qkvb[TTOK * 3 * DM];
__device__ bf16  g_attnOb[TTOK * DM];
__device__ float g_gate[TTOK * DM];
__device__ float g_proj[TTOK * DM];
__device__ float g_xz[TTOK * 2 * DM];
__device__ bf16  g_sactb[TTOK * DM];
__device__ float g_ssm[TTOK * DM];
__device__ float g_u[TTOK * DM];
__device__ bf16  g_minb[TTOK * DM];
__device__ int   g_top_idx[TTOK * 2];
__device__ float g_top_w[TTOK * 2];
__device__ int   g_slot[TTOK * 2];
__device__ int   g_count[EE];
__device__ int   g_fill[EE];
__device__ int   g_seg_start[EE];
__device__ int   g_tile_expert[MAX_TILES];
__device__ int   g_tile_row0[MAX_TILES];
__device__ int   g_num_tiles;
__device__ int   g_assign_tok[AMAX];
__device__ float g_H1[(size_t)AMAX * FF];
__device__ bf16  g_Hb[(size_t)AMAX * FF];
__device__ float g_Y[(size_t)AMAX * DM];

__device__ bf16 g_Wqkvb[DM * 3 * DM];
__device__ bf16 g_Woutb[DM * DM];
__device__ bf16 g_Wgateb[DM * DM];
__device__ bf16 g_Winb[DM * 2 * DM];
__device__ bf16 g_Woutsb[DM * DM];
__device__ bf16 g_W1b[(size_t)EE * DM * FF];
__device__ bf16 g_W2b[(size_t)EE * FF * DM];
__device__ bf16 g_W3b[(size_t)EE * DM * FF];

__device__ __forceinline__ float sigm(float v) { return 1.f / (1.f + expf(-v)); }

// ---------------- mma / async helpers ----------------------------------------
__device__ __forceinline__ unsigned smaddr(const void* p) {
    return (unsigned)__cvta_generic_to_shared(p);
}
__device__ __forceinline__ void cpa16(void* s, const void* g) {
    asm volatile("cp.async.cg.shared.global [%0], [%1], 16;" :: "r"(smaddr(s)), "l"(g));
}
#define CP_COMMIT() asm volatile("cp.async.commit_group;")
template<int N> __device__ __forceinline__ void cp_wait() {
    asm volatile("cp.async.wait_group %0;" :: "n"(N));
}

#define LDSM4(R0,R1,R2,R3,ADDR) \
    asm volatile("ldmatrix.sync.aligned.m8n8.x4.shared.b16 {%0,%1,%2,%3}, [%4];" \
        : "=r"(R0),"=r"(R1),"=r"(R2),"=r"(R3) : "r"(ADDR))
#define LDSM4T(R0,R1,R2,R3,ADDR) \
    asm volatile("ldmatrix.sync.aligned.m8n8.x4.trans.shared.b16 {%0,%1,%2,%3}, [%4];" \
        : "=r"(R0),"=r"(R1),"=r"(R2),"=r"(R3) : "r"(ADDR))

__device__ __forceinline__ void mma16816(float* d, const unsigned* a, const unsigned* b) {
    asm volatile(
        "mma.sync.aligned.m16n8k16.row.col.f32.bf16.bf16.f32 "
        "{%0,%1,%2,%3},{%4,%5,%6,%7},{%8,%9},{%0,%1,%2,%3};"
        : "+f"(d[0]), "+f"(d[1]), "+f"(d[2]), "+f"(d[3])
        : "r"(a[0]), "r"(a[1]), "r"(a[2]), "r"(a[3]), "r"(b[0]), "r"(b[1]));
}

__device__ __forceinline__ void store2(float* p, float x, float y) {
    *reinterpret_cast<float2*>(p) = make_float2(x, y);
}
__device__ __forceinline__ void store2(bf16* p, float x, float y) {
    *reinterpret_cast<__nv_bfloat162*>(p) = __floats2bfloat162_rn(x, y);
}
__device__ __forceinline__ unsigned packbf(float x, float y) {
    __nv_bfloat162 h = __floats2bfloat162_rn(x, y);
    return *reinterpret_cast<unsigned*>(&h);
}

// ---------------- pipelined bf16 GEMM (non-trans B) --------------------------
// C[M,N] = A[M,K] @ B[K,N]; BM=128, BN=128, BK=64, 2-stage cp.async
#define GEMM_SMEM (2*128*(64+8)*2 + 2*64*(128+8)*2)

template<typename OutT>
__global__ __launch_bounds__(256) void mma_gemm(
    const bf16* __restrict__ A, int lda,
    const bf16* __restrict__ B, int ldb,
    OutT* __restrict__ C, int ldc, int K)
{
    constexpr int BM = 128, BN = 128, BK = 64, WN = 64, NT = 8;
    extern __shared__ char smem[];
    auto As = reinterpret_cast<bf16(*)[BM][BK + 8]>(smem);
    auto Bs = reinterpret_cast<bf16(*)[BK][BN + 8]>(smem + 2 * BM * (BK + 8) * 2);
    int row0 = blockIdx.y * BM, col0 = blockIdx.x * BN;
    int tid = threadIdx.x, lane = tid & 31, wid = tid >> 5;
    int wm = wid & 3, wn = wid >> 2;

    auto load_tile = [&](int k0, int s) {
#pragma unroll
        for (int v = tid; v < BM * BK / 8; v += 256) {
            int r = v >> 3, c = (v & 7) * 8;
            cpa16(&As[s][r][c], A + (long)(row0 + r) * lda + k0 + c);
        }
#pragma unroll
        for (int v = tid; v < BK * BN / 8; v += 256) {
            int r = v >> 4, c = (v & 15) * 8;
            cpa16(&Bs[s][r][c], B + (long)(k0 + r) * ldb + col0 + c);
        }
        CP_COMMIT();
    };

    float acc[2][NT][4];
#pragma unroll
    for (int i = 0; i < 2; i++)
#pragma unroll
        for (int j = 0; j < NT; j++)
#pragma unroll
            for (int r = 0; r < 4; r++) acc[i][j][r] = 0.f;

    int nk = K / BK;
    load_tile(0, 0);
    for (int kt = 0; kt < nk; kt++) {
        int cur = kt & 1;
        if (kt + 1 < nk) { load_tile((kt + 1) * BK, cur ^ 1); cp_wait<1>(); }
        else cp_wait<0>();
        __syncthreads();
#pragma unroll
        for (int ks = 0; ks < BK / 16; ks++) {
            unsigned afr[2][4];
#pragma unroll
            for (int mi = 0; mi < 2; mi++) {
                const bf16* p = &As[cur][wm * 32 + mi * 16 + (lane & 15)][ks * 16 + (lane >> 4) * 8];
                LDSM4(afr[mi][0], afr[mi][1], afr[mi][2], afr[mi][3], smaddr(p));
            }
            unsigned bfr[NT][2];
#pragma unroll
            for (int njp = 0; njp < NT / 2; njp++) {
                int nb = wn * WN + njp * 16;
                const bf16* p = &Bs[cur][ks * 16 + (lane & 7) + ((lane >> 3) & 1) * 8][nb + (lane >> 4) * 8];
                LDSM4T(bfr[2*njp][0], bfr[2*njp][1], bfr[2*njp+1][0], bfr[2*njp+1][1], smaddr(p));
            }
#pragma unroll
            for (int mi = 0; mi < 2; mi++)
#pragma unroll
                for (int nj = 0; nj < NT; nj++)
                    mma16816(acc[mi][nj], afr[mi], bfr[nj]);
        }
        __syncthreads();
    }

    int gid = lane >> 2, tig = lane & 3;
#pragma unroll
    for (int mi = 0; mi < 2; mi++)
#pragma unroll
        for (int nj = 0; nj < NT; nj++) {
            int r = row0 + wm * 32 + mi * 16 + gid;
            int c = col0 + wn * WN + nj * 8 + tig * 2;
            store2(C + (long)r * ldc + c, acc[mi][nj][0], acc[mi][nj][1]);
            store2(C + (long)(r + 8) * ldc + c, acc[mi][nj][2], acc[mi][nj][3]);
        }
}

// ---------------- grouped (MoE) pipelined GEMM -------------------------------
// EPI 0: C=float store. EPI 1: read H1, out = silu(h1)*acc -> bf16 store.
#define GGEMM_SMEM (GEMM_SMEM + 512)

template<bool GATHER, int EPI, typename OutT>
__global__ __launch_bounds__(256) void grouped_mma_gemm(
    const bf16* __restrict__ Asrc, int lda,
    const bf16* __restrict__ Wbase, long expStride, int ldb,
    OutT* __restrict__ C, int ldc, int K, const float* __restrict__ Hin)
{
    constexpr int BM = 128, BN = 128, BK = 64, WN = 64, NT = 8;
    extern __shared__ char smem[];
    auto As = reinterpret_cast<bf16(*)[BM][BK + 8]>(smem);
    auto Bs = reinterpret_cast<bf16(*)[BK][BN + 8]>(smem + 2 * BM * (BK + 8) * 2);
    int* rowmap = reinterpret_cast<int*>(smem + GEMM_SMEM);
    if ((int)blockIdx.y >= g_num_tiles) return;
    int e = g_tile_expert[blockIdx.y];
    int row0 = g_tile_row0[blockIdx.y];
    const bf16* Bb = Wbase + (long)e * expStride;
    int col0 = blockIdx.x * BN;
    int tid = threadIdx.x, lane = tid & 31, wid = tid >> 5;
    int wm = wid & 3, wn = wid >> 2;
    if (tid < BM) rowmap[tid] = GATHER ? g_assign_tok[row0 + tid] : (row0 + tid);
    __syncthreads();

    auto load_tile = [&](int k0, int s) {
#pragma unroll
        for (int v = tid; v < BM * BK / 8; v += 256) {
            int r = v >> 3, c = (v & 7) * 8;
            cpa16(&As[s][r][c], Asrc + (long)rowmap[r] * lda + k0 + c);
        }
#pragma unroll
        for (int v = tid; v < BK * BN / 8; v += 256) {
            int r = v >> 4, c = (v & 15) * 8;
            cpa16(&Bs[s][r][c], Bb + (long)(k0 + r) * ldb + col0 + c);
        }
        CP_COMMIT();
    };

    float acc[2][NT][4];
#pragma unroll
    for (int i = 0; i < 2; i++)
#pragma unroll
        for (int j = 0; j < NT; j++)
#pragma unroll
            for (int r = 0; r < 4; r++) acc[i][j][r] = 0.f;

    int nk = K / BK;
    load_tile(0, 0);
    for (int kt = 0; kt < nk; kt++) {
        int cur = kt & 1;
        if (kt + 1 < nk) { load_tile((kt + 1) * BK, cur ^ 1); cp_wait<1>(); }
        else cp_wait<0>();
        __syncthreads();
#pragma unroll
        for (int ks = 0; ks < BK / 16; ks++) {
            unsigned afr[2][4];
#pragma unroll
            for (int mi = 0; mi < 2; mi++) {
                const bf16* p = &As[cur][wm * 32 + mi * 16 + (lane & 15)][ks * 16 + (lane >> 4) * 8];
                LDSM4(afr[mi][0], afr[mi][1], afr[mi][2], afr[mi][3], smaddr(p));
            }
            unsigned bfr[NT][2];
#pragma unroll
            for (int njp = 0; njp < NT / 2; njp++) {
                int nb = wn * WN + njp * 16;
                const bf16* p = &Bs[cur][ks * 16 + (lane & 7) + ((lane >> 3) & 1) * 8][nb + (lane >> 4) * 8];
                LDSM4T(bfr[2*njp][0], bfr[2*njp][1], bfr[2*njp+1][0], bfr[2*njp+1][1], smaddr(p));
            }
#pragma unroll
            for (int mi = 0; mi < 2; mi++)
#pragma unroll
                for (int nj = 0; nj < NT; nj++)
                    mma16816(acc[mi][nj], afr[mi], bfr[nj]);
        }
        __syncthreads();
    }

    int gid = lane >> 2, tig = lane & 3;
#pragma unroll
    for (int mi = 0; mi < 2; mi++)
#pragma unroll
        for (int nj = 0; nj < NT; nj++) {
            int r = row0 + wm * 32 + mi * 16 + gid;
            int c = col0 + wn * WN + nj * 8 + tig * 2;
            if (EPI == 0) {
                store2(C + (long)r * ldc + c, acc[mi][nj][0], acc[mi][nj][1]);
                store2(C + (long)(r + 8) * ldc + c, acc[mi][nj][2], acc[mi][nj][3]);
            } else {
                float2 h0 = *reinterpret_cast<const float2*>(Hin + (long)r * ldc + c);
                float2 h1 = *reinterpret_cast<const float2*>(Hin + (long)(r + 8) * ldc + c);
                store2(C + (long)r * ldc + c,
                       h0.x * sigm(h0.x) * acc[mi][nj][0], h0.y * sigm(h0.y) * acc[mi][nj][1]);
                store2(C + (long)(r + 8) * ldc + c,
                       h1.x * sigm(h1.x) * acc[mi][nj][2], h1.y * sigm(h1.y) * acc[mi][nj][3]);
            }
        }
}

// ---------------- flash attention --------------------------------------------
// grid: (LSEQ/128, 32). 8 warps; warp wm owns 16 q rows. KV tiles of 64.
#define FLASH_SMEM (128*72*2 + 2*64*72*2 + 2*64*72*2)

__global__ __launch_bounds__(256) void flash_kernel(bf16* __restrict__ attnO) {
    extern __shared__ char smem[];
    auto Qs = reinterpret_cast<bf16(*)[72]>(smem);                          // [128][72]
    auto Ks = reinterpret_cast<bf16(*)[64][72]>(smem + 128 * 72 * 2);       // [2][64][72]
    auto Vs = reinterpret_cast<bf16(*)[64][72]>(smem + 128 * 72 * 2 + 2 * 64 * 72 * 2);
    int bh = blockIdx.y;
    int b = bh >> 4, h = bh & 15;
    int q0 = blockIdx.x * 128;
    const bf16* base = g_qkvb + (long)b * LSEQ * 3 * DM + h * HDIM;
    int tid = threadIdx.x, lane = tid & 31, wid = tid >> 5;
    int wm = wid;                          // 8 warps x 16 rows
    int gid = lane >> 2, tig = lane & 3;

    auto loadKV = [&](int t, int s) {
#pragma unroll
        for (int v = tid; v < 512; v += 256) {
            int r = v >> 3, c = (v & 7) * 8;
            cpa16(&Ks[s][r][c], base + DM + (long)(t * 64 + r) * 3 * DM + c);
        }
#pragma unroll
        for (int v = tid; v < 512; v += 256) {
            int r = v >> 3, c = (v & 7) * 8;
            cpa16(&Vs[s][r][c], base + 2 * DM + (long)(t * 64 + r) * 3 * DM + c);
        }
        CP_COMMIT();
    };

    // prologue: Q + KV0 in group 0
#pragma unroll
    for (int v = tid; v < 1024; v += 256) {
        int r = v >> 3, c = (v & 7) * 8;
        cpa16(&Qs[r][c], base + (long)(q0 + r) * 3 * DM + c);
    }
    loadKV(0, 0);

    unsigned qa[4][4];
    float acc[8][4];
#pragma unroll
    for (int j = 0; j < 8; j++)
#pragma unroll
        for (int r = 0; r < 4; r++) acc[j][r] = 0.f;
    float m0 = -1e30f, m1 = -1e30f, l0 = 0.f, l1 = 0.f;

    for (int t = 0; t < 16; t++) {
        int cur = t & 1;
        if (t + 1 < 16) { loadKV(t + 1, cur ^ 1); cp_wait<1>(); }
        else cp_wait<0>();
        __syncthreads();
        if (t == 0) {
#pragma unroll
            for (int ks = 0; ks < 4; ks++) {
                const bf16* p = &Qs[wm * 16 + (lane & 15)][ks * 16 + (lane >> 4) * 8];
                LDSM4(qa[ks][0], qa[ks][1], qa[ks][2], qa[ks][3], smaddr(p));
            }
        }
        // S = Q @ K^T
        float sc[8][4];
#pragma unroll
        for (int j = 0; j < 8; j++)
#pragma unroll
            for (int r = 0; r < 4; r++) sc[j][r] = 0.f;
#pragma unroll
        for (int ks = 0; ks < 4; ks++) {
            unsigned bfr[8][2];
#pragma unroll
            for (int njp = 0; njp < 4; njp++) {
                int nb = njp * 16;
                const bf16* p = &Ks[cur][nb + (lane & 7) + ((lane >> 4) << 3)][ks * 16 + ((lane >> 3) & 1) * 8];
                LDSM4(bfr[2*njp][0], bfr[2*njp][1], bfr[2*njp+1][0], bfr[2*njp+1][1], smaddr(p));
            }
#pragma unroll
            for (int nj = 0; nj < 8; nj++) mma16816(sc[nj], qa[ks], bfr[nj]);
        }
        // online softmax (scale 0.125)
        float tm0 = -1e30f, tm1 = -1e30f;
#pragma unroll
        for (int nj = 0; nj < 8; nj++) {
#pragma unroll
            for (int r = 0; r < 4; r++) sc[nj][r] *= 0.125f;
            tm0 = fmaxf(tm0, fmaxf(sc[nj][0], sc[nj][1]));
            tm1 = fmaxf(tm1, fmaxf(sc[nj][2], sc[nj][3]));
        }
        tm0 = fmaxf(tm0, __shfl_xor_sync(0xffffffffu, tm0, 1));
        tm0 = fmaxf(tm0, __shfl_xor_sync(0xffffffffu, tm0, 2));
        tm1 = fmaxf(tm1, __shfl_xor_sync(0xffffffffu, tm1, 1));
        tm1 = fmaxf(tm1, __shfl_xor_sync(0xffffffffu, tm1, 2));
        float nm0 = fmaxf(m0, tm0), nm1 = fmaxf(m1, tm1);
        float a0 = expf(m0 - nm0), a1 = expf(m1 - nm1);
        float ps0 = 0.f, ps1 = 0.f;
#pragma unroll
        for (int nj = 0; nj < 8; nj++) {
            sc[nj][0] = expf(sc[nj][0] - nm0);
            sc[nj][1] = expf(sc[nj][1] - nm0);
            sc[nj][2] = expf(sc[nj][2] - nm1);
            sc[nj][3] = expf(sc[nj][3] - nm1);
            ps0 += sc[nj][0] + sc[nj][1];
            ps1 += sc[nj][2] + sc[nj][3];
        }
        ps0 += __shfl_xor_sync(0xffffffffu, ps0, 1);
        ps0 += __shfl_xor_sync(0xffffffffu, ps0, 2);
        ps1 += __shfl_xor_sync(0xffffffffu, ps1, 1);
        ps1 += __shfl_xor_sync(0xffffffffu, ps1, 2);
        l0 = l0 * a0 + ps0; l1 = l1 * a1 + ps1;
        m0 = nm0; m1 = nm1;
#pragma unroll
        for (int nj = 0; nj < 8; nj++) {
            acc[nj][0] *= a0; acc[nj][1] *= a0;
            acc[nj][2] *= a1; acc[nj][3] *= a1;
        }
        // P @ V
        unsigned pa[4][4];
#pragma unroll
        for (int ks = 0; ks < 4; ks++) {
            pa[ks][0] = packbf(sc[2*ks][0], sc[2*ks][1]);
            pa[ks][1] = packbf(sc[2*ks][2], sc[2*ks][3]);
            pa[ks][2] = packbf(sc[2*ks+1][0], sc[2*ks+1][1]);
            pa[ks][3] = packbf(sc[2*ks+1][2], sc[2*ks+1][3]);
        }
#pragma unroll
        for (int ks = 0; ks < 4; ks++) {
            unsigned vb[8][2];
#pragma unroll
            for (int njp = 0; njp < 4; njp++) {
                int nb = njp * 16;
                const bf16* p = &Vs[cur][ks * 16 + (lane & 7) + ((lane >> 3) & 1) * 8][nb + (lane >> 4) * 8];
                LDSM4T(vb[2*njp][0], vb[2*njp][1], vb[2*njp+1][0], vb[2*njp+1][1], smaddr(p));
            }
#pragma unroll
            for (int nj = 0; nj < 8; nj++) mma16816(acc[nj], pa[ks], vb[nj]);
        }
        __syncthreads();
    }

    float inv0 = 1.f / l0, inv1 = 1.f / l1;
    long tok0 = (long)b * LSEQ + q0 + wm * 16 + gid;
#pragma unroll
    for (int nj = 0; nj < 8; nj++) {
        int c = h * 64 + nj * 8 + tig * 2;
        store2(attnO + tok0 * DM + c, acc[nj][0] * inv0, acc[nj][1] * inv0);
        store2(attnO + (tok0 + 8) * DM + c, acc[nj][2] * inv1, acc[nj][3] * inv1);
    }
}

// ---------------- elementwise kernels ----------------------------------------

__global__ void zero_kernel() {
    int i = blockIdx.x * blockDim.x + threadIdx.x;
    if (i < EE) { g_count[i] = 0; g_fill[i] = 0; }
    if (i < AMAX) g_assign_tok[i] = 0;
}

__global__ void cvt_kernel(const float4* __restrict__ src, uint4* __restrict__ dst, int n8) {
    int i = blockIdx.x * blockDim.x + threadIdx.x;
    if (i >= n8) return;
    float4 a = src[2 * i], b = src[2 * i + 1];
    union { uint4 u; __nv_bfloat162 h[4]; } o;
    o.h[0] = __floats2bfloat162_rn(a.x, a.y);
    o.h[1] = __floats2bfloat162_rn(a.z, a.w);
    o.h[2] = __floats2bfloat162_rn(b.x, b.y);
    o.h[3] = __floats2bfloat162_rn(b.z, b.w);
    dst[i] = o.u;
}

__global__ void ln_kernel(const float* __restrict__ in, const float* __restrict__ g,
                          const float* __restrict__ b, bf16* __restrict__ out) {
    int t = blockIdx.x, tid = threadIdx.x;
    const float* row = in + (size_t)t * DM;
    float v[4], s = 0.f, s2 = 0.f;
#pragma unroll
    for (int i = 0; i < 4; i++) {
        v[i] = row[tid + i * 256];
        s += v[i]; s2 += v[i] * v[i];
    }
    __shared__ float sh1[256], sh2[256];
    sh1[tid] = s; sh2[tid] = s2;
    __syncthreads();
    for (int o = 128; o > 0; o >>= 1) {
        if (tid < o) { sh1[tid] += sh1[tid + o]; sh2[tid] += sh2[tid + o]; }
        __syncthreads();
    }
    float mean = sh1[0] * (1.f / DM);
    float var = sh2[0] * (1.f / DM) - mean * mean;
    float inv = rsqrtf(var + 1e-5f);
    bf16* orow = out + (size_t)t * DM;
#pragma unroll
    for (int i = 0; i < 4; i++) {
        int d = tid + i * 256;
        orow[d] = __float2bfloat16((v[i] - mean) * inv * g[d] + b[d]);
    }
}

__global__ void alpha_kernel(const float* __restrict__ Wr, const float* __restrict__ br) {
    int t = blockIdx.x, tid = threadIdx.x;
    float s = 0.f;
#pragma unroll
    for (int i = 0; i < 4; i++) {
        int d = tid + i * 256;
        s += __bfloat162float(g_normedb[(size_t)t * DM + d]) * Wr[d * 2];
    }
    __shared__ float sh[256];
    sh[tid] = s; __syncthreads();
    for (int o = 128; o > 0; o >>= 1) {
        if (tid < o) sh[tid] += sh[tid + o];
        __syncthreads();
    }
    if (tid == 0) g_alpha[t] = sigm(sh[0] + br[0]);
}

__global__ void conv_act_kernel(const float* __restrict__ cw, const float* __restrict__ cb) {
    int idx = blockIdx.x * blockDim.x + threadIdx.x;
    int d = idx & (DM - 1);
    int t = idx >> 10;
    int l = t & (LSEQ - 1);
    int b = t >> 10;
    float y = cb[d];
#pragma unroll
    for (int k = 0; k < 4; k++) {
        int ls = l - 3 + k;
        if (ls >= 0) y += cw[d * 4 + k] * g_xz[((size_t)(b * LSEQ + ls)) * (2 * DM) + d];
    }
    float xc = y * sigm(y);
    float z = g_xz[(size_t)t * (2 * DM) + DM + d];
    g_sactb[idx] = __float2bfloat16(xc * sigm(z));
}

__global__ void blend_kernel(const float* __restrict__ x, const float* __restrict__ ls1) {
    int idx = blockIdx.x * blockDim.x + threadIdx.x;
    int t = idx >> 10, d = idx & (DM - 1);
    float a = g_alpha[t];
    float attn = g_proj[idx] * sigm(g_gate[idx]);
    float bl = ls1[d] * ((1.f - a) * g_ssm[idx] + a * attn);
    g_u[idx] = x[idx] + bl;
}

__global__ void gating_kernel(const float* __restrict__ Wg) {
    int t = blockIdx.x, tid = threadIdx.x;
    int lane = tid & 31, w = tid >> 5;
    float s = 0.f;
    for (int d = lane; d < DM; d += 32)
        s += __bfloat162float(g_minb[(size_t)t * DM + d]) * Wg[d * EE + w];
#pragma unroll
    for (int o = 16; o > 0; o >>= 1) s += __shfl_down_sync(0xffffffffu, s, o);
    __shared__ float lg[EE];
    if (lane == 0) lg[w] = s;
    __syncthreads();
    if (tid == 0) {
        float m = lg[0];
        for (int e = 1; e < EE; e++) m = fmaxf(m, lg[e]);
        float p[EE], sum = 0.f;
        for (int e = 0; e < EE; e++) { p[e] = expf(lg[e] - m); sum += p[e]; }
        float inv = 1.f / sum;
        for (int e = 0; e < EE; e++) p[e] *= inv;
        int i0 = 0;
        for (int e = 1; e < EE; e++) if (p[e] > p[i0]) i0 = e;
        int i1 = (i0 == 0) ? 1 : 0;
        for (int e = 0; e < EE; e++) if (e != i0 && p[e] > p[i1]) i1 = e;
        float den = p[i0] + p[i1] + 1e-8f;
        g_top_idx[t * 2] = i0; g_top_idx[t * 2 + 1] = i1;
        g_top_w[t * 2] = p[i0] / den; g_top_w[t * 2 + 1] = p[i1] / den;
        atomicAdd(&g_count[i0], 1);
        atomicAdd(&g_count[i1], 1);
    }
}

__global__ void seg_kernel() {
    if (threadIdx.x == 0 && blockIdx.x == 0) {
        int off = 0, nt = 0;
        for (int e = 0; e < EE; e++) {
            g_seg_start[e] = off;
            int tiles = (g_count[e] + 127) >> 7;
            for (int i = 0; i < tiles; i++) {
                g_tile_expert[nt] = e;
                g_tile_row0[nt] = off + (i << 7);
                nt++;
            }
            off += tiles << 7;
        }
        g_num_tiles = nt;
    }
}

__global__ void scatter_kernel() {
    int t = blockIdx.x * blockDim.x + threadIdx.x;
    if (t >= TTOK) return;
#pragma unroll
    for (int k = 0; k < 2; k++) {
        int e = g_top_idx[t * 2 + k];
        int pos = atomicAdd(&g_fill[e], 1);
        int slot = g_seg_start[e] + pos;
        g_assign_tok[slot] = t;
        g_slot[t * 2 + k] = slot;
    }
}

__global__ void combine_kernel(const float* __restrict__ x, const float* __restrict__ ls2,
                               float* __restrict__ out) {
    int idx = blockIdx.x * blockDim.x + threadIdx.x;
    int t = idx >> 10, d = idx & (DM - 1);
    float moe = g_top_w[t * 2] * g_Y[(size_t)g_slot[t * 2] * DM + d]
              + g_top_w[t * 2 + 1] * g_Y[(size_t)g_slot[t * 2 + 1] * DM + d];
    out[idx] = x[idx] + g_u[idx] + ls2[d] * moe;
}

// ---------------- host launch -------------------------------------------------

template <typename T>
static T* sym(const void* s) {
    void* p = nullptr;
    cudaGetSymbolAddress(&p, s);
    return (T*)p;
}

static void cvt(const float* src, bf16* dst, size_t n) {
    int n8 = (int)(n / 8);
    cvt_kernel<<<(n8 + 255) / 256, 256>>>((const float4*)src, (uint4*)dst, n8);
}

extern "C" void kernel_launch(void* const* d_in, const int* in_sizes, int n_in,
                              void* d_out, int out_size) {
    const float* x       = (const float*)d_in[0];
    const float* Wr      = (const float*)d_in[1];
    const float* br      = (const float*)d_in[2];
    const float* ln1_g   = (const float*)d_in[4];
    const float* ln1_b   = (const float*)d_in[5];
    const float* ln2_g   = (const float*)d_in[6];
    const float* ln2_b   = (const float*)d_in[7];
    const float* ls1     = (const float*)d_in[8];
    const float* ls2     = (const float*)d_in[9];
    const float* Wqkv    = (const float*)d_in[10];
    const float* Wout    = (const float*)d_in[11];
    const float* Wgate   = (const float*)d_in[12];
    const float* Win_ssm = (const float*)d_in[13];
    const float* conv_w  = (const float*)d_in[14];
    const float* conv_b  = (const float*)d_in[15];
    const float* Wout_ssm= (const float*)d_in[16];
    const float* Wg      = (const float*)d_in[17];
    const float* W1      = (const float*)d_in[18];
    const float* W2      = (const float*)d_in[19];
    const float* W3      = (const float*)d_in[20];
    float* out = (float*)d_out;

    bf16*  p_normedb = sym<bf16>(g_normedb);
    bf16*  p_qkvb    = sym<bf16>(g_qkvb);
    bf16*  p_attnOb  = sym<bf16>(g_attnOb);
    float* p_gate    = sym<float>(g_gate);
    float* p_proj    = sym<float>(g_proj);
    float* p_xz      = sym<float>(g_xz);
    bf16*  p_sactb   = sym<bf16>(g_sactb);
    float* p_ssm     = sym<float>(g_ssm);
    float* p_u       = sym<float>(g_u);
    bf16*  p_minb    = sym<bf16>(g_minb);
    float* p_H1      = sym<float>(g_H1);
    bf16*  p_Hb      = sym<bf16>(g_Hb);
    float* p_Y       = sym<float>(g_Y);
    bf16*  p_Wqkvb   = sym<bf16>(g_Wqkvb);
    bf16*  p_Woutb   = sym<bf16>(g_Woutb);
    bf16*  p_Wgateb  = sym<bf16>(g_Wgateb);
    bf16*  p_Winb    = sym<bf16>(g_Winb);
    bf16*  p_Woutsb  = sym<bf16>(g_Woutsb);
    bf16*  p_W1b     = sym<bf16>(g_W1b);
    bf16*  p_W2b     = sym<bf16>(g_W2b);
    bf16*  p_W3b     = sym<bf16>(g_W3b);

    // opt into >48KB dynamic smem (idempotent, not a stream op)
    cudaFuncSetAttribute(mma_gemm<bf16>,  cudaFuncAttributeMaxDynamicSharedMemorySize, GEMM_SMEM);
    cudaFuncSetAttribute(mma_gemm<float>, cudaFuncAttributeMaxDynamicSharedMemorySize, GEMM_SMEM);
    cudaFuncSetAttribute(grouped_mma_gemm<true, 0, float>, cudaFuncAttributeMaxDynamicSharedMemorySize, GGEMM_SMEM);
    cudaFuncSetAttribute(grouped_mma_gemm<true, 1, bf16>,  cudaFuncAttributeMaxDynamicSharedMemorySize, GGEMM_SMEM);
    cudaFuncSetAttribute(grouped_mma_gemm<false, 0, float>, cudaFuncAttributeMaxDynamicSharedMemorySize, GGEMM_SMEM);
    cudaFuncSetAttribute(flash_kernel, cudaFuncAttributeMaxDynamicSharedMemorySize, FLASH_SMEM);

    const int TD = TTOK * DM;

    zero_kernel<<<(AMAX + 255) / 256, 256>>>();
    cvt(Wqkv, p_Wqkvb, (size_t)DM * 3 * DM);
    cvt(Wout, p_Woutb, (size_t)DM * DM);
    cvt(Wgate, p_Wgateb, (size_t)DM * DM);
    cvt(Win_ssm, p_Winb, (size_t)DM * 2 * DM);
    cvt(Wout_ssm, p_Woutsb, (size_t)DM * DM);
    cvt(W1, p_W1b, (size_t)EE * DM * FF);
    cvt(W2, p_W2b, (size_t)EE * FF * DM);
    cvt(W3, p_W3b, (size_t)EE * DM * FF);

    ln_kernel<<<TTOK, 256>>>(x, ln1_g, ln1_b, p_normedb);
    alpha_kernel<<<TTOK, 256>>>(Wr, br);

    // qkv = normed @ Wqkv -> bf16
    mma_gemm<bf16><<<dim3(24, 16), 256, GEMM_SMEM>>>(
        p_normedb, DM, p_Wqkvb, 3 * DM, p_qkvb, 3 * DM, DM);
    // fused attention
    flash_kernel<<<dim3(LSEQ / 128, 32), 256, FLASH_SMEM>>>(p_attnOb);
    // gate / proj
    mma_gemm<float><<<dim3(8, 16), 256, GEMM_SMEM>>>(
        p_normedb, DM, p_Wgateb, DM, p_gate, DM, DM);
    mma_gemm<float><<<dim3(8, 16), 256, GEMM_SMEM>>>(
        p_attnOb, DM, p_Woutb, DM, p_proj, DM, DM);
    // xz = normed @ Win_ssm
    mma_gemm<float><<<dim3(16, 16), 256, GEMM_SMEM>>>(
        p_normedb, DM, p_Winb, 2 * DM, p_xz, 2 * DM, DM);
    conv_act_kernel<<<TD / 256, 256>>>(conv_w, conv_b);
    mma_gemm<float><<<dim3(8, 16), 256, GEMM_SMEM>>>(
        p_sactb, DM, p_Woutsb, DM, p_ssm, DM, DM);
    blend_kernel<<<TD / 256, 256>>>(x, ls1);
    ln_kernel<<<TTOK, 256>>>(p_u, ln2_g, ln2_b, p_minb);

    // MoE
    gating_kernel<<<TTOK, 256>>>(Wg);
    seg_kernel<<<1, 32>>>();
    scatter_kernel<<<TTOK / 256, 256>>>();
    grouped_mma_gemm<true, 0, float><<<dim3(FF / 128, MAX_TILES), 256, GGEMM_SMEM>>>(
        p_minb, DM, p_W1b, (long)DM * FF, FF, p_H1, FF, DM, nullptr);
    grouped_mma_gemm<true, 1, bf16><<<dim3(FF / 128, MAX_TILES), 256, GGEMM_SMEM>>>(
        p_minb, DM, p_W3b, (long)DM * FF, FF, p_Hb, FF, DM, p_H1);
    grouped_mma_gemm<false, 0, float><<<dim3(DM / 128, MAX_TILES), 256, GGEMM_SMEM>>>(
        p_Hb, FF, p_W2b, (long)FF * DM, DM, p_Y, DM, FF, nullptr);
    combine_kernel<<<TD / 256, 256>>>(x, ls2, out);
}